// round 15
// baseline (speedup 1.0000x reference)
#include <cuda_runtime.h>

#define AALPHA 0.42f
#define IMG_H 1024
#define IMG_W 1024
#define NIMG 48     // 16 batches * 3 masks
#define RPB 64      // output rows per block
#define BPI 16      // blocks per image (IMG_H / RPB)

__device__ float g_part[NIMG * BPI];
__device__ float g_weights[NIMG];

// sigmoid(x) = 0.5*tanh(x/2)+0.5  (1 MUFU + 2 fma)
__device__ __forceinline__ float fsig(float x) {
    float t;
    asm("tanh.approx.f32 %0, %1;" : "=f"(t) : "f"(0.5f * x));
    return fmaf(0.5f, t, 0.5f);
}
__device__ __forceinline__ float fsqrt_fast(float x) {
    float r; asm("sqrt.approx.f32 %0, %1;" : "=f"(r) : "f"(x)); return r;
}

// ---------------------------------------------------------------------------
// score = ALPHA * sum(edge) + (1-ALPHA)/49 * sum( cnt(p) * (m_p - mean_p)^2 )
// OCCUPANCY round: single-row pipeline, h-sum ring moved from 32 registers to
// private smem (each thread touches only its own 4 columns -> no extra sync),
// cwf recomputed at the end. __launch_bounds__(256,3) -> 3 blocks/SM,
// 24 warps/SM (was 16). Own-row m kept in registers (B never re-read).
// ---------------------------------------------------------------------------
__global__ __launch_bounds__(256, 3) void score_kernel(const float* __restrict__ logits) {
    __shared__ float rowbuf[2][1032];   // sigmoid rows, cols -4..1027 at +4
    __shared__ float hrbuf[8][1024];    // horizontal-7-sum ring (private/thread)
    __shared__ float red[8];

    const int img = blockIdx.y;
    const int y0  = blockIdx.x * RPB;
    const int t   = threadIdx.x;
    const int c0  = t * 4;
    const float* base = logits + (size_t)img * (IMG_H * IMG_W);

    // zero halo columns of both row buffers: idx {0..3, 1028..1031}
    if (t < 16) {
        int b = t >> 3, j = t & 7;
        rowbuf[b][(j < 4) ? j : (1024 + j)] = 0.0f;
    }
    // zero own hr slots (private columns, no sync needed before first use
    // beyond the barrier already inside the row loop)
    float* hrp = &hrbuf[0][c0];
    #pragma unroll
    for (int k = 0; k < 8; ++k)
        *(float4*)(hrp + k * 1024) = make_float4(0.f, 0.f, 0.f, 0.f);

    float rs[4][4], rt[4][4], rc[4][4];  // conv combo ring (registers)
    float vs[4] = {0.f, 0.f, 0.f, 0.f};
    #pragma unroll
    for (int k = 0; k < 4; ++k) {
        #pragma unroll
        for (int j = 0; j < 4; ++j) { rs[k][j]=0.f; rt[k][j]=0.f; rc[k][j]=0.f; }
    }

    float acc;

    if (blockIdx.x >= 1 && blockIdx.x <= 14) {
        // ================= clean path: all rows in-bounds, chf = 7 =========
        float accv[4] = {0.f, 0.f, 0.f, 0.f};
        float acc_e = 0.f, acc_l = 0.f;

        const float* rp = base + (size_t)(y0 - 3) * IMG_W + c0;
        float4 cur = *(const float4*)rp; rp += IMG_W;   // row 0

// one row; U, DOOUT, DOPREF are literals
#define ROW_CLEAN(U, DOOUT, DOPREF)                                         \
    do {                                                                    \
        float4 nxt;                                                         \
        if (DOPREF) { nxt = *(const float4*)rp; rp += IMG_W; }              \
        else        { nxt = make_float4(0.f, 0.f, 0.f, 0.f); }              \
        float m0 = fsig(cur.x), m1 = fsig(cur.y);                           \
        float m2 = fsig(cur.z), m3 = fsig(cur.w);                           \
        float* rb = rowbuf[(U) & 1];                                        \
        *(float4*)(rb + 4 + c0) = make_float4(m0, m1, m2, m3);              \
        __syncthreads();                                                    \
        const float4 A   = *(const float4*)(rb + c0);                       \
        const float4 C   = *(const float4*)(rb + c0 + 8);                   \
        const float4 hro = *(const float4*)(hrp + (((U) + 1) & 7) * 1024);  \
        float h0 = ((A.y + A.z) + (A.w + m0)) + ((m1 + m2) + m3);           \
        float h1 = h0 + C.x - A.y;                                          \
        float h2 = h1 + C.y - A.z;                                          \
        float h3 = h2 + C.z - A.w;                                          \
        vs[0] += h0 - hro.x;                                                \
        vs[1] += h1 - hro.y;                                                \
        vs[2] += h2 - hro.z;                                                \
        vs[3] += h3 - hro.w;                                                \
        *(float4*)(hrp + ((U) & 7) * 1024) = make_float4(h0, h1, h2, h3);   \
        if (DOOUT) {                                                        \
            const int T = (U) & 3, M = ((U) + 1) & 3, Bo = ((U) + 2) & 3;   \
            _Pragma("unroll")                                               \
            for (int j = 0; j < 4; ++j) {                                   \
                float gxv = fmaf(2.f, rt[M][j], rt[T][j] + rt[Bo][j]);      \
                float gyv = rs[T][j] - rs[Bo][j];                           \
                float lap = fmaf(-6.f, rc[M][j],                            \
                                 (rc[T][j] + rc[Bo][j]) + rs[M][j]);        \
                acc_e += fsqrt_fast(fmaf(gxv, gxv, gyv * gyv));             \
                acc_l += fabsf(lap);                                        \
                float d = fmaf(-(1.f / 49.f), vs[j], rc[M][j]);             \
                accv[j] = fmaf(d, d, accv[j]);                              \
            }                                                               \
        }                                                                   \
        const int W = (U) & 3;                                              \
        rs[W][0] = fmaf(2.f, m0, A.w + m1); rt[W][0] = A.w - m1; rc[W][0] = m0; \
        rs[W][1] = fmaf(2.f, m1, m0 + m2);  rt[W][1] = m0 - m2;  rc[W][1] = m1; \
        rs[W][2] = fmaf(2.f, m2, m1 + m3);  rt[W][2] = m1 - m3;  rc[W][2] = m2; \
        rs[W][3] = fmaf(2.f, m3, m2 + C.x); rt[W][3] = m2 - C.x; rc[W][3] = m3; \
        cur = nxt;                                                          \
    } while (0)

        // prologue rows 0..7 (outputs at rows 6,7)
        ROW_CLEAN(0, false, true); ROW_CLEAN(1, false, true);
        ROW_CLEAN(2, false, true); ROW_CLEAN(3, false, true);
        ROW_CLEAN(4, false, true); ROW_CLEAN(5, false, true);
        ROW_CLEAN(6, true,  true); ROW_CLEAN(7, true,  true);

        // middle rows 8..63
        for (int ii = 8; ii < 64; ii += 8) {
            ROW_CLEAN(0, true, true); ROW_CLEAN(1, true, true);
            ROW_CLEAN(2, true, true); ROW_CLEAN(3, true, true);
            ROW_CLEAN(4, true, true); ROW_CLEAN(5, true, true);
            ROW_CLEAN(6, true, true); ROW_CLEAN(7, true, true);
        }

        // tail rows 64..69 (row 68 prefetches row 69; row 69 none)
        ROW_CLEAN(0, true, true); ROW_CLEAN(1, true, true);
        ROW_CLEAN(2, true, true); ROW_CLEAN(3, true, true);
        ROW_CLEAN(4, true, true); ROW_CLEAN(5, true, false);
#undef ROW_CLEAN

        // fold cw/7 per column (recomputed) and 0.5*|lap|
        float acc_v_tot = 0.f;
        #pragma unroll
        for (int j = 0; j < 4; ++j) {
            int col = c0 + j;
            float cwn = (float)(min(col, 3) + min(IMG_W - 1 - col, 3) + 1) * (1.0f / 7.0f);
            acc_v_tot = fmaf(accv[j], cwn, acc_v_tot);
        }
        float acc_e_tot = fmaf(0.5f, acc_l, acc_e);
        acc = AALPHA * acc_e_tot + ((1.0f - AALPHA) / 49.0f) * 7.0f * acc_v_tot;
    } else {
        // ================= guarded path (blocks 0 and 15), per-row =========
        float acc_e = 0.f, acc_l = 0.f, acc_v = 0.f;
        float cwf[4];
        #pragma unroll
        for (int j = 0; j < 4; ++j) {
            int col = c0 + j;
            cwf[j] = (float)(min(col, 3) + min(IMG_W - 1 - col, 3) + 1);
        }

        float4 cur = make_float4(0.f, 0.f, 0.f, 0.f);
        {
            int gy = y0 - 3;
            if ((unsigned)gy < IMG_H)
                cur = *(const float4*)(base + (size_t)gy * IMG_W + c0);
        }
        for (int ii = 0; ii < 72; ii += 8) {
            #pragma unroll
            for (int u = 0; u < 8; ++u) {
                const int i  = ii + u;
                const int gy = y0 - 3 + i;
                const bool valid = ((unsigned)gy < IMG_H) && (i < 70);

                float4 nxt = make_float4(0.f, 0.f, 0.f, 0.f);
                {
                    int gyn = gy + 1;
                    if ((unsigned)gyn < IMG_H && (i + 1) < 70)
                        nxt = *(const float4*)(base + (size_t)gyn * IMG_W + c0);
                }
                float m0 = valid ? fsig(cur.x) : 0.f;
                float m1 = valid ? fsig(cur.y) : 0.f;
                float m2 = valid ? fsig(cur.z) : 0.f;
                float m3 = valid ? fsig(cur.w) : 0.f;
                float* rb = rowbuf[u & 1];
                *(float4*)(rb + 4 + c0) = make_float4(m0, m1, m2, m3);
                __syncthreads();

                const float4 A   = *(const float4*)(rb + c0);
                const float4 C   = *(const float4*)(rb + c0 + 8);
                const float4 hro = *(const float4*)(hrp + ((u + 1) & 7) * 1024);

                float h0 = ((A.y + A.z) + (A.w + m0)) + ((m1 + m2) + m3);
                float h1 = h0 + C.x - A.y;
                float h2 = h1 + C.y - A.z;
                float h3 = h2 + C.z - A.w;

                vs[0] += h0 - hro.x;
                vs[1] += h1 - hro.y;
                vs[2] += h2 - hro.z;
                vs[3] += h3 - hro.w;
                *(float4*)(hrp + (u & 7) * 1024) = make_float4(h0, h1, h2, h3);

                if (i >= 6 && i < 70) {
                    const int yo = gy - 3;
                    const float chf = (float)(min(yo, 3) + min(IMG_H - 1 - yo, 3) + 1);
                    const int T = u & 3, M = (u + 1) & 3, Bo = (u + 2) & 3;
                    float rowv = 0.f;
                    #pragma unroll
                    for (int j = 0; j < 4; ++j) {
                        float gxv = fmaf(2.f, rt[M][j], rt[T][j] + rt[Bo][j]);
                        float gyv = rs[T][j] - rs[Bo][j];
                        float lap = fmaf(-6.f, rc[M][j], (rc[T][j] + rc[Bo][j]) + rs[M][j]);
                        acc_e += fsqrt_fast(fmaf(gxv, gxv, gyv * gyv));
                        acc_l += fabsf(lap);
                        float d = fmaf(-(1.f / 49.f), vs[j], rc[M][j]);
                        rowv = fmaf(d * cwf[j], d, rowv);
                    }
                    acc_v += chf * rowv;
                }

                const int W = u & 3;
                rs[W][0] = fmaf(2.f, m0, A.w + m1); rt[W][0] = A.w - m1; rc[W][0] = m0;
                rs[W][1] = fmaf(2.f, m1, m0 + m2);  rt[W][1] = m0 - m2;  rc[W][1] = m1;
                rs[W][2] = fmaf(2.f, m2, m1 + m3);  rt[W][2] = m1 - m3;  rc[W][2] = m2;
                rs[W][3] = fmaf(2.f, m3, m2 + C.x); rt[W][3] = m2 - C.x; rc[W][3] = m3;

                cur = nxt;
            }
        }
        float acc_e_tot = fmaf(0.5f, acc_l, acc_e);
        acc = AALPHA * acc_e_tot + ((1.0f - AALPHA) / 49.0f) * acc_v;
    }

    // block reduction -> per-block partial
    #pragma unroll
    for (int off = 16; off; off >>= 1)
        acc += __shfl_down_sync(0xffffffffu, acc, off);
    if ((t & 31) == 0) red[t >> 5] = acc;
    __syncthreads();
    if (t < 8) {
        float v = red[t];
        #pragma unroll
        for (int off = 4; off; off >>= 1)
            v += __shfl_down_sync(0xffu, v, off);
        if (t == 0) g_part[img * BPI + blockIdx.x] = v;
    }
}

// ---------------------------------------------------------------------------
// reduce partials; weights[b,s] = 0.5*(score/(sum+1e-6) + softmax(lw)[s])
// ---------------------------------------------------------------------------
__global__ void weights_kernel(const float* __restrict__ lw) {
    __shared__ float ss[NIMG];
    __shared__ float soft[3];
    int tid = threadIdx.x;
    if (tid < NIMG) {
        float s = 0.f;
        #pragma unroll
        for (int k = 0; k < BPI; ++k) s += g_part[tid * BPI + k];
        ss[tid] = s;
    }
    if (tid == 0) {
        float a = lw[0], b = lw[1], c = lw[2];
        float m = fmaxf(a, fmaxf(b, c));
        float e0 = expf(a - m), e1 = expf(b - m), e2 = expf(c - m);
        float inv = 1.0f / (e0 + e1 + e2);
        soft[0] = e0 * inv; soft[1] = e1 * inv; soft[2] = e2 * inv;
    }
    __syncthreads();
    if (tid < NIMG) {
        int b = tid / 3;
        int s = tid - b * 3;
        float denom = ss[b * 3] + ss[b * 3 + 1] + ss[b * 3 + 2] + 1e-6f;
        g_weights[tid] = (ss[tid] / denom + soft[s]) * 0.5f;
    }
}

// ---------------------------------------------------------------------------
// fused[b,p] = sum_s logits[b,s,p] * w[b,s]   (float4 vectorized)
// ---------------------------------------------------------------------------
__global__ __launch_bounds__(256) void fuse_kernel(const float* __restrict__ logits,
                                                   float* __restrict__ out) {
    const int N = IMG_H * IMG_W;
    int b = blockIdx.y;
    int i = blockIdx.x * blockDim.x + threadIdx.x;   // over N/4
    float w0 = g_weights[b * 3 + 0];
    float w1 = g_weights[b * 3 + 1];
    float w2 = g_weights[b * 3 + 2];
    const float4* p0 = (const float4*)(logits + (size_t)(b * 3 + 0) * N);
    const float4* p1 = (const float4*)(logits + (size_t)(b * 3 + 1) * N);
    const float4* p2 = (const float4*)(logits + (size_t)(b * 3 + 2) * N);
    float4 a = p0[i], bb = p1[i], cc = p2[i];
    float4 o;
    o.x = a.x * w0 + bb.x * w1 + cc.x * w2;
    o.y = a.y * w0 + bb.y * w1 + cc.y * w2;
    o.z = a.z * w0 + bb.z * w1 + cc.z * w2;
    o.w = a.w * w0 + bb.w * w1 + cc.w * w2;
    ((float4*)out)[(size_t)b * (N / 4) + i] = o;
}

extern "C" void kernel_launch(void* const* d_in, const int* in_sizes, int n_in,
                              void* d_out, int out_size) {
    const float* logits = (const float*)d_in[0];   // (16,3,1024,1024) fp32
    const float* lw     = (const float*)d_in[1];   // (3,) fp32
    float* out          = (float*)d_out;           // (16,1024,1024) fp32

    score_kernel<<<dim3(BPI, NIMG), 256>>>(logits);
    weights_kernel<<<1, 64>>>(lw);
    fuse_kernel<<<dim3((IMG_H * IMG_W / 4) / 256, 16), 256>>>(logits, out);
}

// round 16
// speedup vs baseline: 1.0430x; 1.0430x over previous
#include <cuda_runtime.h>

#define AALPHA 0.42f
#define IMG_H 1024
#define IMG_W 1024
#define NIMG 48     // 16 batches * 3 masks
#define SPI 6       // strips per image -> 288 blocks = ONE wave at occ 2

__device__ float g_part[NIMG * SPI];
__device__ float g_weights[NIMG];

// sigmoid(x) = 0.5*tanh(x/2)+0.5  (1 MUFU + 2 fma)
__device__ __forceinline__ float fsig(float x) {
    float t;
    asm("tanh.approx.f32 %0, %1;" : "=f"(t) : "f"(0.5f * x));
    return fmaf(0.5f, t, 0.5f);
}
__device__ __forceinline__ float fsqrt_fast(float x) {
    float r; asm("sqrt.approx.f32 %0, %1;" : "=f"(r) : "f"(x)); return r;
}

// ---------------------------------------------------------------------------
// score = ALPHA * sum(edge) + (1-ALPHA)/49 * sum( cnt(p) * (m_p - mean_p)^2 )
// SINGLE-WAVE layout: 6 strips/image (~171 rows each), 288 blocks total =
// one full wave at 2 blocks/SM (was 768 blocks = 2.59 waves -> 3). Warm-up
// drops 8.6% -> 3.4% of rows. R10 register pipeline; dynamic trip count with
// cheap per-row predicates (prefetch i+1<niter, output 6<=i<niter).
// Interior strips (1..4) skip all image-boundary checks; strips 0,5 guarded.
// ---------------------------------------------------------------------------
__global__ __launch_bounds__(256, 2) void score_kernel(const float* __restrict__ logits) {
    __shared__ float rowbuf[2][1032];   // cols -4..1027, data at offset 4
    __shared__ float red[8];

    const int img = blockIdx.y;
    const int s   = blockIdx.x;
    const int r0  = (s * IMG_H) / SPI;          // first output row
    const int r1  = ((s + 1) * IMG_H) / SPI;    // one past last output row
    const int niter = (r1 - r0) + 6;            // 176 or 177 row-iterations
    const int t   = threadIdx.x;
    const int c0  = t * 4;
    const float* base = logits + (size_t)img * (IMG_H * IMG_W);

    // zero halo columns of both buffers: idx {0..3, 1028..1031}
    if (t < 16) {
        int b = t >> 3, j = t & 7;
        rowbuf[b][(j < 4) ? j : (1024 + j)] = 0.0f;
    }

    float hr[8][4];                      // horizontal-7-sum ring (registers)
    float rs[4][4], rt[4][4], rc[4][4];  // conv combo ring
    float vs[4] = {0.f, 0.f, 0.f, 0.f};
    #pragma unroll
    for (int k = 0; k < 8; ++k) { hr[k][0]=hr[k][1]=hr[k][2]=hr[k][3]=0.f; }
    #pragma unroll
    for (int k = 0; k < 4; ++k) {
        #pragma unroll
        for (int j = 0; j < 4; ++j) { rs[k][j]=0.f; rt[k][j]=0.f; rc[k][j]=0.f; }
    }

    float acc;

    if (s >= 1 && s <= 4) {
        // ============ interior strips: every load in-bounds, chf = 7 =======
        float accv[4] = {0.f, 0.f, 0.f, 0.f};
        float acc_e = 0.f, acc_l = 0.f;

        const float* rp = base + (size_t)(r0 - 3) * IMG_W + c0;
        float4 cur = *(const float4*)rp; rp += IMG_W;   // row i=0 (gy=r0-3)

#define ROW_CLEAN(U)                                                        \
    do {                                                                    \
        const int i = ii + (U);                                             \
        float4 nxt = make_float4(0.f, 0.f, 0.f, 0.f);                       \
        if (i + 1 < niter) { nxt = *(const float4*)rp; rp += IMG_W; }       \
        float m0 = fsig(cur.x), m1 = fsig(cur.y);                           \
        float m2 = fsig(cur.z), m3 = fsig(cur.w);                           \
        float* rb = rowbuf[(U) & 1];                                        \
        *(float4*)(rb + 4 + c0) = make_float4(m0, m1, m2, m3);              \
        __syncthreads();                                                    \
        const float4 A = *(const float4*)(rb + c0);                         \
        const float4 C = *(const float4*)(rb + c0 + 8);                     \
        float h0 = ((A.y + A.z) + (A.w + m0)) + ((m1 + m2) + m3);           \
        float h1 = h0 + C.x - A.y;                                          \
        float h2 = h1 + C.y - A.z;                                          \
        float h3 = h2 + C.z - A.w;                                          \
        vs[0] += h0 - hr[((U) + 1) & 7][0];                                 \
        vs[1] += h1 - hr[((U) + 1) & 7][1];                                 \
        vs[2] += h2 - hr[((U) + 1) & 7][2];                                 \
        vs[3] += h3 - hr[((U) + 1) & 7][3];                                 \
        hr[(U) & 7][0] = h0; hr[(U) & 7][1] = h1;                           \
        hr[(U) & 7][2] = h2; hr[(U) & 7][3] = h3;                           \
        if (i >= 6 && i < niter) {                                          \
            const int T = (U) & 3, M = ((U) + 1) & 3, Bo = ((U) + 2) & 3;   \
            _Pragma("unroll")                                               \
            for (int j = 0; j < 4; ++j) {                                   \
                float gxv = fmaf(2.f, rt[M][j], rt[T][j] + rt[Bo][j]);      \
                float gyv = rs[T][j] - rs[Bo][j];                           \
                float lap = fmaf(-6.f, rc[M][j],                            \
                                 (rc[T][j] + rc[Bo][j]) + rs[M][j]);        \
                acc_e += fsqrt_fast(fmaf(gxv, gxv, gyv * gyv));             \
                acc_l += fabsf(lap);                                        \
                float d = fmaf(-(1.f / 49.f), vs[j], rc[M][j]);             \
                accv[j] = fmaf(d, d, accv[j]);                              \
            }                                                               \
        }                                                                   \
        const int W = (U) & 3;                                              \
        rs[W][0] = fmaf(2.f, m0, A.w + m1); rt[W][0] = A.w - m1; rc[W][0] = m0; \
        rs[W][1] = fmaf(2.f, m1, m0 + m2);  rt[W][1] = m0 - m2;  rc[W][1] = m1; \
        rs[W][2] = fmaf(2.f, m2, m1 + m3);  rt[W][2] = m1 - m3;  rc[W][2] = m2; \
        rs[W][3] = fmaf(2.f, m3, m2 + C.x); rt[W][3] = m2 - C.x; rc[W][3] = m3; \
        cur = nxt;                                                          \
    } while (0)

        for (int ii = 0; ii < niter; ii += 8) {
            ROW_CLEAN(0); ROW_CLEAN(1); ROW_CLEAN(2); ROW_CLEAN(3);
            ROW_CLEAN(4); ROW_CLEAN(5); ROW_CLEAN(6); ROW_CLEAN(7);
        }
#undef ROW_CLEAN

        // fold cw/7 per column and 0.5*|lap|; chf == 7 folded into scale
        float acc_v_tot = 0.f;
        #pragma unroll
        for (int j = 0; j < 4; ++j) {
            int col = c0 + j;
            float cwn = (float)(min(col, 3) + min(IMG_W - 1 - col, 3) + 1) * (1.0f / 7.0f);
            acc_v_tot = fmaf(accv[j], cwn, acc_v_tot);
        }
        float acc_e_tot = fmaf(0.5f, acc_l, acc_e);
        acc = AALPHA * acc_e_tot + ((1.0f - AALPHA) / 49.0f) * 7.0f * acc_v_tot;
    } else {
        // ============ boundary strips (s = 0, 5): guarded ==================
        float acc_e = 0.f, acc_l = 0.f, acc_v = 0.f;
        float cwf[4];
        #pragma unroll
        for (int j = 0; j < 4; ++j) {
            int col = c0 + j;
            cwf[j] = (float)(min(col, 3) + min(IMG_W - 1 - col, 3) + 1);
        }

        float4 cur = make_float4(0.f, 0.f, 0.f, 0.f);
        {
            int gy = r0 - 3;
            if ((unsigned)gy < IMG_H)
                cur = *(const float4*)(base + (size_t)gy * IMG_W + c0);
        }

#define ROW_GUARD(U)                                                        \
    do {                                                                    \
        const int i  = ii + (U);                                            \
        const int gy = r0 - 3 + i;                                          \
        const bool valid = ((unsigned)gy < IMG_H) && (i < niter);           \
        float4 nxt = make_float4(0.f, 0.f, 0.f, 0.f);                       \
        {                                                                   \
            int gyn = gy + 1;                                               \
            if ((unsigned)gyn < IMG_H && (i + 1) < niter)                   \
                nxt = *(const float4*)(base + (size_t)gyn * IMG_W + c0);    \
        }                                                                   \
        float m0 = valid ? fsig(cur.x) : 0.f;                               \
        float m1 = valid ? fsig(cur.y) : 0.f;                               \
        float m2 = valid ? fsig(cur.z) : 0.f;                               \
        float m3 = valid ? fsig(cur.w) : 0.f;                               \
        float* rb = rowbuf[(U) & 1];                                        \
        *(float4*)(rb + 4 + c0) = make_float4(m0, m1, m2, m3);              \
        __syncthreads();                                                    \
        const float4 A = *(const float4*)(rb + c0);                         \
        const float4 C = *(const float4*)(rb + c0 + 8);                     \
        float h0 = ((A.y + A.z) + (A.w + m0)) + ((m1 + m2) + m3);           \
        float h1 = h0 + C.x - A.y;                                          \
        float h2 = h1 + C.y - A.z;                                          \
        float h3 = h2 + C.z - A.w;                                          \
        vs[0] += h0 - hr[((U) + 1) & 7][0];                                 \
        vs[1] += h1 - hr[((U) + 1) & 7][1];                                 \
        vs[2] += h2 - hr[((U) + 1) & 7][2];                                 \
        vs[3] += h3 - hr[((U) + 1) & 7][3];                                 \
        hr[(U) & 7][0] = h0; hr[(U) & 7][1] = h1;                           \
        hr[(U) & 7][2] = h2; hr[(U) & 7][3] = h3;                           \
        if (i >= 6 && i < niter) {                                          \
            const int yo = gy - 3;                                          \
            const float chf = (float)(min(yo, 3) + min(IMG_H - 1 - yo, 3) + 1); \
            const int T = (U) & 3, M = ((U) + 1) & 3, Bo = ((U) + 2) & 3;   \
            float rowv = 0.f;                                               \
            _Pragma("unroll")                                               \
            for (int j = 0; j < 4; ++j) {                                   \
                float gxv = fmaf(2.f, rt[M][j], rt[T][j] + rt[Bo][j]);      \
                float gyv = rs[T][j] - rs[Bo][j];                           \
                float lap = fmaf(-6.f, rc[M][j],                            \
                                 (rc[T][j] + rc[Bo][j]) + rs[M][j]);        \
                acc_e += fsqrt_fast(fmaf(gxv, gxv, gyv * gyv));             \
                acc_l += fabsf(lap);                                        \
                float d = fmaf(-(1.f / 49.f), vs[j], rc[M][j]);             \
                rowv = fmaf(d * cwf[j], d, rowv);                           \
            }                                                               \
            acc_v += chf * rowv;                                            \
        }                                                                   \
        const int W = (U) & 3;                                              \
        rs[W][0] = fmaf(2.f, m0, A.w + m1); rt[W][0] = A.w - m1; rc[W][0] = m0; \
        rs[W][1] = fmaf(2.f, m1, m0 + m2);  rt[W][1] = m0 - m2;  rc[W][1] = m1; \
        rs[W][2] = fmaf(2.f, m2, m1 + m3);  rt[W][2] = m1 - m3;  rc[W][2] = m2; \
        rs[W][3] = fmaf(2.f, m3, m2 + C.x); rt[W][3] = m2 - C.x; rc[W][3] = m3; \
        cur = nxt;                                                          \
    } while (0)

        for (int ii = 0; ii < niter; ii += 8) {
            ROW_GUARD(0); ROW_GUARD(1); ROW_GUARD(2); ROW_GUARD(3);
            ROW_GUARD(4); ROW_GUARD(5); ROW_GUARD(6); ROW_GUARD(7);
        }
#undef ROW_GUARD

        float acc_e_tot = fmaf(0.5f, acc_l, acc_e);
        acc = AALPHA * acc_e_tot + ((1.0f - AALPHA) / 49.0f) * acc_v;
    }

    // block reduction -> per-strip partial
    #pragma unroll
    for (int off = 16; off; off >>= 1)
        acc += __shfl_down_sync(0xffffffffu, acc, off);
    if ((t & 31) == 0) red[t >> 5] = acc;
    __syncthreads();
    if (t < 8) {
        float v = red[t];
        #pragma unroll
        for (int off = 4; off; off >>= 1)
            v += __shfl_down_sync(0xffu, v, off);
        if (t == 0) g_part[img * SPI + blockIdx.x] = v;
    }
}

// ---------------------------------------------------------------------------
// reduce partials; weights[b,s] = 0.5*(score/(sum+1e-6) + softmax(lw)[s])
// ---------------------------------------------------------------------------
__global__ void weights_kernel(const float* __restrict__ lw) {
    __shared__ float ss[NIMG];
    __shared__ float soft[3];
    int tid = threadIdx.x;
    if (tid < NIMG) {
        float s = 0.f;
        #pragma unroll
        for (int k = 0; k < SPI; ++k) s += g_part[tid * SPI + k];
        ss[tid] = s;
    }
    if (tid == 0) {
        float a = lw[0], b = lw[1], c = lw[2];
        float m = fmaxf(a, fmaxf(b, c));
        float e0 = expf(a - m), e1 = expf(b - m), e2 = expf(c - m);
        float inv = 1.0f / (e0 + e1 + e2);
        soft[0] = e0 * inv; soft[1] = e1 * inv; soft[2] = e2 * inv;
    }
    __syncthreads();
    if (tid < NIMG) {
        int b = tid / 3;
        int s = tid - b * 3;
        float denom = ss[b * 3] + ss[b * 3 + 1] + ss[b * 3 + 2] + 1e-6f;
        g_weights[tid] = (ss[tid] / denom + soft[s]) * 0.5f;
    }
}

// ---------------------------------------------------------------------------
// fused[b,p] = sum_s logits[b,s,p] * w[b,s]   (float4 vectorized)
// ---------------------------------------------------------------------------
__global__ __launch_bounds__(256) void fuse_kernel(const float* __restrict__ logits,
                                                   float* __restrict__ out) {
    const int N = IMG_H * IMG_W;
    int b = blockIdx.y;
    int i = blockIdx.x * blockDim.x + threadIdx.x;   // over N/4
    float w0 = g_weights[b * 3 + 0];
    float w1 = g_weights[b * 3 + 1];
    float w2 = g_weights[b * 3 + 2];
    const float4* p0 = (const float4*)(logits + (size_t)(b * 3 + 0) * N);
    const float4* p1 = (const float4*)(logits + (size_t)(b * 3 + 1) * N);
    const float4* p2 = (const float4*)(logits + (size_t)(b * 3 + 2) * N);
    float4 a = p0[i], bb = p1[i], cc = p2[i];
    float4 o;
    o.x = a.x * w0 + bb.x * w1 + cc.x * w2;
    o.y = a.y * w0 + bb.y * w1 + cc.y * w2;
    o.z = a.z * w0 + bb.z * w1 + cc.z * w2;
    o.w = a.w * w0 + bb.w * w1 + cc.w * w2;
    ((float4*)out)[(size_t)b * (N / 4) + i] = o;
}

extern "C" void kernel_launch(void* const* d_in, const int* in_sizes, int n_in,
                              void* d_out, int out_size) {
    const float* logits = (const float*)d_in[0];   // (16,3,1024,1024) fp32
    const float* lw     = (const float*)d_in[1];   // (3,) fp32
    float* out          = (float*)d_out;           // (16,1024,1024) fp32

    score_kernel<<<dim3(SPI, NIMG), 256>>>(logits);
    weights_kernel<<<1, 64>>>(lw);
    fuse_kernel<<<dim3((IMG_H * IMG_W / 4) / 256, 16), 256>>>(logits, out);
}

// round 17
// speedup vs baseline: 1.2544x; 1.2027x over previous
#include <cuda_runtime.h>

#define AALPHA 0.42f
#define IMG_H 1024
#define IMG_W 1024
#define NIMG 48     // 16 batches * 3 masks
#define SPI 6       // strips per image -> 288 blocks = ONE wave at occ 2

__device__ float g_part[NIMG * SPI];
__device__ float g_weights[NIMG];

// sigmoid(x) = 0.5*tanh(x/2)+0.5  (1 MUFU + 2 fma)
__device__ __forceinline__ float fsig(float x) {
    float t;
    asm("tanh.approx.f32 %0, %1;" : "=f"(t) : "f"(0.5f * x));
    return fmaf(0.5f, t, 0.5f);
}
__device__ __forceinline__ float fsqrt_fast(float x) {
    float r; asm("sqrt.approx.f32 %0, %1;" : "=f"(r) : "f"(x)); return r;
}

// ---------------------------------------------------------------------------
// score = ALPHA * sum(edge) + (1-ALPHA)/49 * sum( cnt(p)*(m_p - mean_p)^2 )
// SINGLE WAVE, STATIC BODIES: 6 strips/image, heights {168,176,176,168,168,
// 168} (rows 0..167 | 168..343 | 344..519 | 520..687 | 688..855 | 856..1023),
// so every strip = prologue(8) + K*8 + tail(6), K in {20,21} — all row
// bodies fully static (R10 register pipeline). Image-boundary rows are
// handled by compile-time per-row flags: s=0 prologue has 3 zero rows and
// literal ch/7 weights (4/7,5/7,6/7); s=5 tail symmetric. Variance weight is
// EXACT: accv += (ch/7)*d^2, folded by 7*cw at the end (fixes the factor-7
// bias present since R5's clean path).
// ---------------------------------------------------------------------------
__global__ __launch_bounds__(256, 2) void score_kernel(const float* __restrict__ logits) {
    __shared__ float rowbuf[2][1032];   // cols -4..1027, data at offset 4
    __shared__ float red[8];

    const int img = blockIdx.y;
    const int s   = blockIdx.x;
    // r0 table {0,168,344,520,688,856}
    const int r0  = s * 168 + ((s >= 2) ? 8 : 0) + ((s >= 3) ? 8 : 0);
    const int t   = threadIdx.x;
    const int c0  = t * 4;
    const float* base = logits + (size_t)img * (IMG_H * IMG_W);

    // zero halo columns of both buffers: idx {0..3, 1028..1031}
    if (t < 16) {
        int b = t >> 3, j = t & 7;
        rowbuf[b][(j < 4) ? j : (1024 + j)] = 0.0f;
    }

    float hr[8][4];                      // horizontal-7-sum ring (registers)
    float rs[4][4], rt[4][4], rc[4][4];  // conv combo ring
    float vs[4] = {0.f, 0.f, 0.f, 0.f};
    float accv[4] = {0.f, 0.f, 0.f, 0.f};
    float acc_e = 0.f, acc_l = 0.f;
    #pragma unroll
    for (int k = 0; k < 8; ++k) { hr[k][0]=hr[k][1]=hr[k][2]=hr[k][3]=0.f; }
    #pragma unroll
    for (int k = 0; k < 4; ++k) {
        #pragma unroll
        for (int j = 0; j < 4; ++j) { rs[k][j]=0.f; rt[k][j]=0.f; rc[k][j]=0.f; }
    }

    const float* rp;
    float4 cur;

// one row; ALL flags are literals. VCUR: row in image; DOPREF: prefetch next;
// DOOUT: emit output; CHW: ch/7 weight for this output row (literal).
#define ROWX(U, VCUR, DOPREF, DOOUT, CHW)                                   \
    do {                                                                    \
        float4 nxt;                                                         \
        if (DOPREF) { nxt = *(const float4*)rp; rp += IMG_W; }              \
        else        { nxt = make_float4(0.f, 0.f, 0.f, 0.f); }              \
        float m0, m1, m2, m3;                                               \
        if (VCUR) { m0 = fsig(cur.x); m1 = fsig(cur.y);                     \
                    m2 = fsig(cur.z); m3 = fsig(cur.w); }                   \
        else      { m0 = 0.f; m1 = 0.f; m2 = 0.f; m3 = 0.f; }               \
        float* rb = rowbuf[(U) & 1];                                        \
        *(float4*)(rb + 4 + c0) = make_float4(m0, m1, m2, m3);              \
        __syncthreads();                                                    \
        const float4 A = *(const float4*)(rb + c0);                         \
        const float4 C = *(const float4*)(rb + c0 + 8);                     \
        float h0 = ((A.y + A.z) + (A.w + m0)) + ((m1 + m2) + m3);           \
        float h1 = h0 + C.x - A.y;                                          \
        float h2 = h1 + C.y - A.z;                                          \
        float h3 = h2 + C.z - A.w;                                          \
        vs[0] += h0 - hr[((U) + 1) & 7][0];                                 \
        vs[1] += h1 - hr[((U) + 1) & 7][1];                                 \
        vs[2] += h2 - hr[((U) + 1) & 7][2];                                 \
        vs[3] += h3 - hr[((U) + 1) & 7][3];                                 \
        hr[(U) & 7][0] = h0; hr[(U) & 7][1] = h1;                           \
        hr[(U) & 7][2] = h2; hr[(U) & 7][3] = h3;                           \
        if (DOOUT) {                                                        \
            const int T = (U) & 3, M = ((U) + 1) & 3, Bo = ((U) + 2) & 3;   \
            _Pragma("unroll")                                               \
            for (int j = 0; j < 4; ++j) {                                   \
                float gxv = fmaf(2.f, rt[M][j], rt[T][j] + rt[Bo][j]);      \
                float gyv = rs[T][j] - rs[Bo][j];                           \
                float lap = fmaf(-6.f, rc[M][j],                            \
                                 (rc[T][j] + rc[Bo][j]) + rs[M][j]);        \
                acc_e += fsqrt_fast(fmaf(gxv, gxv, gyv * gyv));             \
                acc_l += fabsf(lap);                                        \
                float d = fmaf(-(1.f / 49.f), vs[j], rc[M][j]);             \
                accv[j] = fmaf(d * (CHW), d, accv[j]);                      \
            }                                                               \
        }                                                                   \
        const int W = (U) & 3;                                              \
        rs[W][0] = fmaf(2.f, m0, A.w + m1); rt[W][0] = A.w - m1; rc[W][0] = m0; \
        rs[W][1] = fmaf(2.f, m1, m0 + m2);  rt[W][1] = m0 - m2;  rc[W][1] = m1; \
        rs[W][2] = fmaf(2.f, m2, m1 + m3);  rt[W][2] = m1 - m3;  rc[W][2] = m2; \
        rs[W][3] = fmaf(2.f, m3, m2 + C.x); rt[W][3] = m2 - C.x; rc[W][3] = m3; \
        cur = nxt;                                                          \
    } while (0)

#define CHUNK8_CLEAN()                                                      \
    do {                                                                    \
        ROWX(0, true, true, true, 1.0f); ROWX(1, true, true, true, 1.0f);   \
        ROWX(2, true, true, true, 1.0f); ROWX(3, true, true, true, 1.0f);   \
        ROWX(4, true, true, true, 1.0f); ROWX(5, true, true, true, 1.0f);   \
        ROWX(6, true, true, true, 1.0f); ROWX(7, true, true, true, 1.0f);   \
    } while (0)

    if (s == 0) {
        // rows 0..167; image top boundary. gy = i-3.
        rp = base + c0;                            // first valid row (0)
        cur = make_float4(0.f, 0.f, 0.f, 0.f);     // i=0 is gy=-3 (zero)
        // prologue i=0..7: rows -3..4. valid from i=3; pf valid from i=2.
        ROWX(0, false, false, false, 1.0f);
        ROWX(1, false, false, false, 1.0f);
        ROWX(2, false, true,  false, 1.0f);
        ROWX(3, true,  true,  false, 1.0f);
        ROWX(4, true,  true,  false, 1.0f);
        ROWX(5, true,  true,  false, 1.0f);
        ROWX(6, true,  true,  true,  (4.0f / 7.0f));   // yo=0, ch=4
        ROWX(7, true,  true,  true,  (5.0f / 7.0f));   // yo=1, ch=5
        // edge chunk i=8..15 (yo=2..9): yo=2 has ch=6
        ROWX(0, true, true, true, (6.0f / 7.0f));
        ROWX(1, true, true, true, 1.0f); ROWX(2, true, true, true, 1.0f);
        ROWX(3, true, true, true, 1.0f); ROWX(4, true, true, true, 1.0f);
        ROWX(5, true, true, true, 1.0f); ROWX(6, true, true, true, 1.0f);
        ROWX(7, true, true, true, 1.0f);
        // 19 clean chunks: i=16..167
        for (int ii = 0; ii < 19; ++ii) CHUNK8_CLEAN();
        // tail i=168..173 (yo=162..167, interior; pf targets <= row 171, valid)
        ROWX(0, true, true, true, 1.0f); ROWX(1, true, true, true, 1.0f);
        ROWX(2, true, true, true, 1.0f); ROWX(3, true, true, true, 1.0f);
        ROWX(4, true, true, true, 1.0f); ROWX(5, true, false, true, 1.0f);
    } else if (s == 5) {
        // rows 856..1023; image bottom boundary. gy = 853+i.
        rp = base + (size_t)(r0 - 3) * IMG_W + c0;
        cur = *(const float4*)rp; rp += IMG_W;
        // clean prologue i=0..7 (outputs yo=856,857 interior)
        ROWX(0, true, true, false, 1.0f); ROWX(1, true, true, false, 1.0f);
        ROWX(2, true, true, false, 1.0f); ROWX(3, true, true, false, 1.0f);
        ROWX(4, true, true, false, 1.0f); ROWX(5, true, true, false, 1.0f);
        ROWX(6, true, true, true,  1.0f); ROWX(7, true, true, true,  1.0f);
        // 20 clean chunks: i=8..167
        for (int ii = 0; ii < 20; ++ii) CHUNK8_CLEAN();
        // tail i=168..173: gy=1021..1026; rows >1023 zero; pf stops at 1023.
        ROWX(0, true,  true,  true, 1.0f);          // gy=1021, pf 1022
        ROWX(1, true,  true,  true, 1.0f);          // gy=1022, pf 1023
        ROWX(2, true,  false, true, 1.0f);          // gy=1023, pf 1024 -> no
        ROWX(3, false, false, true, (6.0f / 7.0f)); // yo=1021, ch=6
        ROWX(4, false, false, true, (5.0f / 7.0f)); // yo=1022, ch=5
        ROWX(5, false, false, true, (4.0f / 7.0f)); // yo=1023, ch=4
    } else {
        // interior strips: s=1,2 -> K=21 (176 rows); s=3,4 -> K=20 (168 rows)
        const int K = (s <= 2) ? 21 : 20;
        rp = base + (size_t)(r0 - 3) * IMG_W + c0;
        cur = *(const float4*)rp; rp += IMG_W;
        // clean prologue i=0..7
        ROWX(0, true, true, false, 1.0f); ROWX(1, true, true, false, 1.0f);
        ROWX(2, true, true, false, 1.0f); ROWX(3, true, true, false, 1.0f);
        ROWX(4, true, true, false, 1.0f); ROWX(5, true, true, false, 1.0f);
        ROWX(6, true, true, true,  1.0f); ROWX(7, true, true, true,  1.0f);
        // K clean chunks
        for (int ii = 0; ii < K; ++ii) CHUNK8_CLEAN();
        // tail 6 (pf targets at most r1+2 <= 858, always valid in-image)
        ROWX(0, true, true, true, 1.0f); ROWX(1, true, true, true, 1.0f);
        ROWX(2, true, true, true, 1.0f); ROWX(3, true, true, true, 1.0f);
        ROWX(4, true, true, true, 1.0f); ROWX(5, true, false, true, 1.0f);
    }
#undef CHUNK8_CLEAN
#undef ROWX

    // fold exact weights: variance term = sum ch*cw*d^2 (accv carries ch/7)
    float acc_v_tot = 0.f;
    #pragma unroll
    for (int j = 0; j < 4; ++j) {
        int col = c0 + j;
        float cwf = (float)(min(col, 3) + min(IMG_W - 1 - col, 3) + 1);
        acc_v_tot = fmaf(accv[j], cwf, acc_v_tot);
    }
    float acc_e_tot = fmaf(0.5f, acc_l, acc_e);
    float acc = AALPHA * acc_e_tot
              + ((1.0f - AALPHA) / 49.0f) * 7.0f * acc_v_tot;

    // block reduction -> per-strip partial
    #pragma unroll
    for (int off = 16; off; off >>= 1)
        acc += __shfl_down_sync(0xffffffffu, acc, off);
    if ((t & 31) == 0) red[t >> 5] = acc;
    __syncthreads();
    if (t < 8) {
        float v = red[t];
        #pragma unroll
        for (int off = 4; off; off >>= 1)
            v += __shfl_down_sync(0xffu, v, off);
        if (t == 0) g_part[img * SPI + blockIdx.x] = v;
    }
}

// ---------------------------------------------------------------------------
// reduce partials; weights[b,s] = 0.5*(score/(sum+1e-6) + softmax(lw)[s])
// ---------------------------------------------------------------------------
__global__ void weights_kernel(const float* __restrict__ lw) {
    __shared__ float ss[NIMG];
    __shared__ float soft[3];
    int tid = threadIdx.x;
    if (tid < NIMG) {
        float s = 0.f;
        #pragma unroll
        for (int k = 0; k < SPI; ++k) s += g_part[tid * SPI + k];
        ss[tid] = s;
    }
    if (tid == 0) {
        float a = lw[0], b = lw[1], c = lw[2];
        float m = fmaxf(a, fmaxf(b, c));
        float e0 = expf(a - m), e1 = expf(b - m), e2 = expf(c - m);
        float inv = 1.0f / (e0 + e1 + e2);
        soft[0] = e0 * inv; soft[1] = e1 * inv; soft[2] = e2 * inv;
    }
    __syncthreads();
    if (tid < NIMG) {
        int b = tid / 3;
        int s = tid - b * 3;
        float denom = ss[b * 3] + ss[b * 3 + 1] + ss[b * 3 + 2] + 1e-6f;
        g_weights[tid] = (ss[tid] / denom + soft[s]) * 0.5f;
    }
}

// ---------------------------------------------------------------------------
// fused[b,p] = sum_s logits[b,s,p] * w[b,s]   (float4 vectorized)
// ---------------------------------------------------------------------------
__global__ __launch_bounds__(256) void fuse_kernel(const float* __restrict__ logits,
                                                   float* __restrict__ out) {
    const int N = IMG_H * IMG_W;
    int b = blockIdx.y;
    int i = blockIdx.x * blockDim.x + threadIdx.x;   // over N/4
    float w0 = g_weights[b * 3 + 0];
    float w1 = g_weights[b * 3 + 1];
    float w2 = g_weights[b * 3 + 2];
    const float4* p0 = (const float4*)(logits + (size_t)(b * 3 + 0) * N);
    const float4* p1 = (const float4*)(logits + (size_t)(b * 3 + 1) * N);
    const float4* p2 = (const float4*)(logits + (size_t)(b * 3 + 2) * N);
    float4 a = p0[i], bb = p1[i], cc = p2[i];
    float4 o;
    o.x = a.x * w0 + bb.x * w1 + cc.x * w2;
    o.y = a.y * w0 + bb.y * w1 + cc.y * w2;
    o.z = a.z * w0 + bb.z * w1 + cc.z * w2;
    o.w = a.w * w0 + bb.w * w1 + cc.w * w2;
    ((float4*)out)[(size_t)b * (N / 4) + i] = o;
}

extern "C" void kernel_launch(void* const* d_in, const int* in_sizes, int n_in,
                              void* d_out, int out_size) {
    const float* logits = (const float*)d_in[0];   // (16,3,1024,1024) fp32
    const float* lw     = (const float*)d_in[1];   // (3,) fp32
    float* out          = (float*)d_out;           // (16,1024,1024) fp32

    score_kernel<<<dim3(SPI, NIMG), 256>>>(logits);
    weights_kernel<<<1, 64>>>(lw);
    fuse_kernel<<<dim3((IMG_H * IMG_W / 4) / 256, 16), 256>>>(logits, out);
}